// round 1
// baseline (speedup 1.0000x reference)
#include <cuda_runtime.h>
#include <math.h>

#define BATCH 32
#define PRI   8732
#define NCLS_TOT 81
#define NCLS  80          // classes 1..80 (class 0 = background, all zeros)
#define KTOP  200
#define CONF_TH 0.01f
#define NMS_TH  0.45f
#define CAND_MAX 1024
#define NBINS 4096

// Scratch (allocation-free rule: __device__ globals)
__device__ float  g_scoresT[(size_t)BATCH * NCLS * PRI];   // ~89 MB, [b][c-1][p], thresholded
__device__ float4 g_boxes[BATCH * PRI];                    // decoded corner-form boxes

// ---------------------------------------------------------------------------
// Decode: cxcy = pr.xy + l.xy*0.1*pr.zw ; wh = pr.zw*exp(l.zw*0.2)
// ---------------------------------------------------------------------------
__global__ void decode_kernel(const float4* __restrict__ loc,
                              const float4* __restrict__ priors) {
    int i = blockIdx.x * blockDim.x + threadIdx.x;
    if (i >= BATCH * PRI) return;
    int p = i % PRI;
    float4 l  = loc[i];
    float4 pr = priors[p];
    float cx = pr.x + (l.x * 0.1f) * pr.z;
    float cy = pr.y + (l.y * 0.1f) * pr.w;
    float w  = pr.z * expf(l.z * 0.2f);
    float h  = pr.w * expf(l.w * 0.2f);
    float x1 = cx - w * 0.5f;
    float y1 = cy - h * 0.5f;
    g_boxes[i] = make_float4(x1, y1, x1 + w, y1 + h);
}

// ---------------------------------------------------------------------------
// Transpose + threshold: conf[b*P+p][c] -> g_scoresT[b][c-1][p] (0 if <= 0.01)
// Tiles of 64 rows x 81 cols through SMEM; both sides coalesced.
// ---------------------------------------------------------------------------
__global__ void transpose_kernel(const float* __restrict__ conf) {
    __shared__ float tile[64 * NCLS_TOT];
    int b  = blockIdx.y;
    int p0 = blockIdx.x * 64;
    int nr = min(64, PRI - p0);
    const float* src = conf + (size_t)(b * PRI + p0) * NCLS_TOT;
    for (int t = threadIdx.x; t < nr * NCLS_TOT; t += blockDim.x) {
        float v = src[t];
        tile[t] = (v > CONF_TH) ? v : 0.0f;
    }
    __syncthreads();
    for (int t = threadIdx.x; t < nr * NCLS; t += blockDim.x) {
        int cc = t / nr;          // 0..79 -> class cc+1
        int r  = t % nr;
        g_scoresT[(size_t)(b * NCLS + cc) * PRI + p0 + r] = tile[r * NCLS_TOT + cc + 1];
    }
}

// ---------------------------------------------------------------------------
// Zero the background-class (class 0) output slabs.
// ---------------------------------------------------------------------------
__global__ void zero_bg_kernel(float* __restrict__ out) {
    int i = blockIdx.x * blockDim.x + threadIdx.x;
    if (i >= BATCH * KTOP * 5) return;
    int b = i / (KTOP * 5);
    int r = i % (KTOP * 5);
    out[(size_t)b * NCLS_TOT * KTOP * 5 + r] = 0.0f;
}

// ---------------------------------------------------------------------------
// Per-(b,c) task: histogram select -> gather -> bitonic sort -> greedy NMS ->
// compact & write 200x5 rows.
// ---------------------------------------------------------------------------
__global__ void __launch_bounds__(256) nms_kernel(float* __restrict__ out) {
    __shared__ unsigned hist[NBINS];
    __shared__ unsigned chunkS[256];
    __shared__ unsigned long long cand[CAND_MAX];
    __shared__ float4 sBox[KTOP];
    __shared__ float  sArea[KTOP];
    __shared__ float  sScore[KTOP];
    __shared__ int    sKeep[KTOP];
    __shared__ int    sDest[KTOP];
    __shared__ unsigned s_binT;
    __shared__ unsigned s_ncand;

    const int task = blockIdx.x;           // 0 .. BATCH*NCLS-1
    const int b    = task / NCLS;
    const int cc   = task % NCLS;          // class cc+1
    const int tid  = threadIdx.x;
    const float* sc = g_scoresT + (size_t)task * PRI;

    for (int t = tid; t < NBINS; t += 256) hist[t] = 0;
    for (int t = tid; t < CAND_MAX; t += 256) cand[t] = 0ULL;
    if (tid == 0) s_ncand = 0;
    __syncthreads();

    // Pass 1: histogram on top-12 bits of float pattern (positive -> monotonic)
    for (int p = tid; p < PRI; p += 256) {
        float v = sc[p];
        if (v > 0.0f) {
            unsigned bits = __float_as_uint(v);
            atomicAdd(&hist[bits >> 20], 1u);
        }
    }
    __syncthreads();

    // Suffix-count select: largest bin bT with count(bin >= bT) >= KTOP
    unsigned part = 0;
    #pragma unroll
    for (int r = 0; r < NBINS / 256; r++) part += hist[tid * (NBINS / 256) + r];
    chunkS[tid] = part;
    __syncthreads();
    if (tid == 0) {
        unsigned cum = 0, bT = 0;
        int found = 0;
        for (int ch = 255; ch >= 0 && !found; ch--) {
            if (cum + chunkS[ch] >= KTOP) {
                for (int bb = ch * 16 + 15; bb >= ch * 16; bb--) {
                    cum += hist[bb];
                    if (cum >= KTOP) { bT = (unsigned)bb; found = 1; break; }
                }
            } else {
                cum += chunkS[ch];
            }
        }
        s_binT = found ? bT : 0u;   // total < K -> gather everything positive
    }
    __syncthreads();
    const unsigned binT = s_binT;

    // Pass 2: gather candidates in bins >= binT (expected ~<300, cap 1024)
    for (int p = tid; p < PRI; p += 256) {
        float v = sc[p];
        if (v > 0.0f) {
            unsigned bits = __float_as_uint(v);
            if ((bits >> 20) >= binT) {
                unsigned pos = atomicAdd(&s_ncand, 1u);
                if (pos < CAND_MAX)
                    cand[pos] = ((unsigned long long)bits << 32) | (unsigned)(~(unsigned)p);
            }
        }
    }
    __syncthreads();

    // Bitonic ascending sort of CAND_MAX keys. key = (valbits<<32)|~idx:
    // descending read-out gives value-desc then index-asc (== jax top_k order).
    for (int kk = 2; kk <= CAND_MAX; kk <<= 1) {
        for (int jj = kk >> 1; jj > 0; jj >>= 1) {
            for (int i = tid; i < CAND_MAX; i += 256) {
                int ixj = i ^ jj;
                if (ixj > i) {
                    unsigned long long a = cand[i], bb = cand[ixj];
                    bool up = ((i & kk) == 0);
                    if ((a > bb) == up) { cand[i] = bb; cand[ixj] = a; }
                }
            }
            __syncthreads();
        }
    }

    int m = (int)min(s_ncand, (unsigned)CAND_MAX);
    int n = min(m, KTOP);

    // Load top-n boxes into SMEM
    for (int k = tid; k < n; k += 256) {
        unsigned long long key = cand[CAND_MAX - 1 - k];
        unsigned bits = (unsigned)(key >> 32);
        int p = (int)(~(unsigned)key);
        float4 bx = g_boxes[b * PRI + p];
        sBox[k]   = bx;
        sScore[k] = __uint_as_float(bits);
        sArea[k]  = (bx.z - bx.x) * (bx.w - bx.y);
        sKeep[k]  = 1;
    }
    __syncthreads();

    // Greedy NMS (division-free: inter > T*(ai+aj-inter); denominator > 0)
    for (int i = 0; i < n; i++) {
        if (sKeep[i]) {
            float4 bi = sBox[i];
            float  ai = sArea[i];
            for (int j = i + 1 + tid; j < n; j += 256) {
                if (sKeep[j]) {
                    float4 bj = sBox[j];
                    float w = fminf(bi.z, bj.z) - fmaxf(bi.x, bj.x);
                    float h = fminf(bi.w, bj.w) - fmaxf(bi.y, bj.y);
                    w = fmaxf(w, 0.0f); h = fmaxf(h, 0.0f);
                    float inter = w * h;
                    if (inter > NMS_TH * (ai + sArea[j] - inter)) sKeep[j] = 0;
                }
            }
        }
        __syncthreads();
    }

    // Compact destinations
    if (tid == 0) {
        int cnt = 0;
        for (int k = 0; k < n; k++) sDest[k] = sKeep[k] ? cnt++ : -1;
    }
    __syncthreads();

    // Write this task's 200x5 slab: zero, then scatter kept rows to front
    float* outBase = out + (size_t)(b * NCLS_TOT + cc + 1) * KTOP * 5;
    for (int t = tid; t < KTOP * 5; t += 256) outBase[t] = 0.0f;
    __syncthreads();
    for (int k = tid; k < n; k += 256) {
        int d = sDest[k];
        if (d >= 0) {
            float* r = outBase + d * 5;
            float4 bx = sBox[k];
            r[0] = sScore[k];
            r[1] = bx.x; r[2] = bx.y; r[3] = bx.z; r[4] = bx.w;
        }
    }
}

// ---------------------------------------------------------------------------
extern "C" void kernel_launch(void* const* d_in, const int* in_sizes, int n_in,
                              void* d_out, int out_size) {
    const float4* loc   = (const float4*)d_in[0];   // [B, P, 4]
    const float*  conf  = (const float*)d_in[1];    // [B*P, C]
    const float4* prior = (const float4*)d_in[2];   // [P, 4]
    float* out = (float*)d_out;                     // [B, C, K, 5]

    decode_kernel<<<(BATCH * PRI + 255) / 256, 256>>>(loc, prior);

    dim3 tg((PRI + 63) / 64, BATCH);
    transpose_kernel<<<tg, 256>>>(conf);

    zero_bg_kernel<<<(BATCH * KTOP * 5 + 255) / 256, 256>>>(out);

    nms_kernel<<<BATCH * NCLS, 256>>>(out);
}

// round 2
// speedup vs baseline: 1.2770x; 1.2770x over previous
#include <cuda_runtime.h>
#include <math.h>

#define BATCH 32
#define PRI   8732
#define NCLS_TOT 81
#define NCLS  80          // classes 1..80 (class 0 = background, all zeros)
#define KTOP  200
#define CONF_TH 0.01f
#define NMS_TH  0.45f
#define CAND_MAX 1024     // coarse candidate cap
#define CAND2   256       // refined candidate cap (sorted set)
#define NBINS 4096

// Scratch (allocation-free rule: __device__ globals)
__device__ float  g_scoresT[(size_t)BATCH * NCLS * PRI];   // [b][c-1][p], thresholded
__device__ float4 g_boxes[BATCH * PRI];                    // decoded corner-form boxes

// ---------------------------------------------------------------------------
__global__ void decode_kernel(const float4* __restrict__ loc,
                              const float4* __restrict__ priors) {
    int i = blockIdx.x * blockDim.x + threadIdx.x;
    if (i >= BATCH * PRI) return;
    int p = i % PRI;
    float4 l  = loc[i];
    float4 pr = priors[p];
    float cx = pr.x + (l.x * 0.1f) * pr.z;
    float cy = pr.y + (l.y * 0.1f) * pr.w;
    float w  = pr.z * expf(l.z * 0.2f);
    float h  = pr.w * expf(l.w * 0.2f);
    float x1 = cx - w * 0.5f;
    float y1 = cy - h * 0.5f;
    g_boxes[i] = make_float4(x1, y1, x1 + w, y1 + h);
}

// ---------------------------------------------------------------------------
__global__ void transpose_kernel(const float* __restrict__ conf) {
    __shared__ float tile[64 * NCLS_TOT];
    int b  = blockIdx.y;
    int p0 = blockIdx.x * 64;
    int nr = min(64, PRI - p0);
    const float* src = conf + (size_t)(b * PRI + p0) * NCLS_TOT;
    for (int t = threadIdx.x; t < nr * NCLS_TOT; t += blockDim.x) {
        float v = src[t];
        tile[t] = (v > CONF_TH) ? v : 0.0f;
    }
    __syncthreads();
    for (int t = threadIdx.x; t < nr * NCLS; t += blockDim.x) {
        int cc = t / nr;
        int r  = t % nr;
        g_scoresT[(size_t)(b * NCLS + cc) * PRI + p0 + r] = tile[r * NCLS_TOT + cc + 1];
    }
}

// ---------------------------------------------------------------------------
__global__ void zero_bg_kernel(float* __restrict__ out) {
    int i = blockIdx.x * blockDim.x + threadIdx.x;
    if (i >= BATCH * KTOP * 5) return;
    int b = i / (KTOP * 5);
    int r = i % (KTOP * 5);
    out[(size_t)b * NCLS_TOT * KTOP * 5 + r] = 0.0f;
}

// ---------------------------------------------------------------------------
// Per-(b,c): coarse hist -> gather -> fine hist (SMEM) -> compact<=256 ->
// register bitonic sort -> suppression bitmask -> serial greedy scan ->
// popcount compaction -> write 200x5 slab.
// ---------------------------------------------------------------------------
__global__ void __launch_bounds__(256) nms_kernel(float* __restrict__ out) {
    __shared__ unsigned hist[NBINS];                 // 16 KB
    __shared__ unsigned chunkS[256];                 // 1 KB
    __shared__ unsigned long long buf[CAND_MAX];     // 8 KB: coarse cands, later NMS mask
    __shared__ unsigned long long cand2[CAND2];      // 2 KB: refined cands / sort scratch
    __shared__ float4 sBox[KTOP];                    // 3.2 KB
    __shared__ float  sArea[KTOP];
    __shared__ float  sScore[KTOP];
    __shared__ unsigned long long sKeepW[4];
    __shared__ unsigned s_binT, s_above, s_fcut, s_ncand, s_n2;
    __shared__ int s_found;

    const int task = blockIdx.x;
    const int b    = task / NCLS;
    const int cc   = task % NCLS;
    const int tid  = threadIdx.x;
    const int wid  = tid >> 5;
    const int lane = tid & 31;
    const float* sc = g_scoresT + (size_t)task * PRI;

    for (int t = tid; t < NBINS; t += 256) hist[t] = 0;
    for (int t = tid; t < CAND2; t += 256) cand2[t] = 0ULL;
    if (tid == 0) s_ncand = 0;
    __syncthreads();

    // ---- coarse histogram on top-12 bits of positive float pattern ----
    for (int p = tid; p < PRI; p += 256) {
        float v = sc[p];
        if (v > 0.0f) atomicAdd(&hist[__float_as_uint(v) >> 20], 1u);
    }
    __syncthreads();

    unsigned part = 0;
    #pragma unroll
    for (int r = 0; r < NBINS / 256; r++) part += hist[tid * (NBINS / 256) + r];
    chunkS[tid] = part;
    __syncthreads();

    if (tid == 0) {
        unsigned cum = 0, bT = 0; int found = 0;
        for (int ch = 255; ch >= 0; ch--) {
            unsigned cs = chunkS[ch];
            if (cum + cs >= KTOP) {
                for (int bb = ch * 16 + 15; bb >= ch * 16; bb--) {
                    cum += hist[bb];
                    if (cum >= KTOP) { bT = (unsigned)bb; found = 1; break; }
                }
                break;
            }
            cum += cs;
        }
        s_binT  = found ? bT : 0u;
        s_found = found;
        s_above = found ? (cum - hist[bT]) : 0u;   // strictly-above-cut count (<K)
        s_n2    = 0;
    }
    __syncthreads();
    const unsigned binT = s_binT;

    // ---- gather coarse candidates (bins >= binT) ----
    for (int p = tid; p < PRI; p += 256) {
        float v = sc[p];
        if (v > 0.0f) {
            unsigned bits = __float_as_uint(v);
            if ((bits >> 20) >= binT) {
                unsigned pos = atomicAdd(&s_ncand, 1u);
                if (pos < CAND_MAX)
                    buf[pos] = ((unsigned long long)bits << 32) | (unsigned)(~(unsigned)p);
            }
        }
    }
    __syncthreads();
    const int gcount = (int)min(s_ncand, (unsigned)CAND_MAX);

    // ---- fine refinement (next 12 bits) within the cut bin, SMEM only ----
    if (s_found) {
        for (int t = tid; t < NBINS; t += 256) hist[t] = 0;
        __syncthreads();
        for (int t = tid; t < gcount; t += 256) {
            unsigned bits = (unsigned)(buf[t] >> 32);
            if ((bits >> 20) == binT) atomicAdd(&hist[(bits >> 8) & 0xFFFu], 1u);
        }
        __syncthreads();
        unsigned fp = 0;
        #pragma unroll
        for (int r = 0; r < NBINS / 256; r++) fp += hist[tid * (NBINS / 256) + r];
        chunkS[tid] = fp;
        __syncthreads();
        if (tid == 0) {
            unsigned need = KTOP - s_above;
            unsigned cum = 0, fc = 0;
            for (int ch = 255; ch >= 0; ch--) {
                unsigned cs = chunkS[ch];
                if (cum + cs >= need) {
                    for (int bb = ch * 16 + 15; bb >= ch * 16; bb--) {
                        cum += hist[bb];
                        if (cum >= need) { fc = (unsigned)bb; break; }
                    }
                    break;
                }
                cum += cs;
            }
            s_fcut = fc;
        }
        __syncthreads();
    }
    const unsigned fcut = s_found ? s_fcut : 0u;

    // ---- compact refined candidates into cand2 (<=256) ----
    for (int t = tid; t < gcount; t += 256) {
        unsigned long long key = buf[t];
        unsigned bits = (unsigned)(key >> 32);
        unsigned cb = bits >> 20;
        if (cb > binT || (cb == binT && ((bits >> 8) & 0xFFFu) >= fcut)) {
            unsigned pos = atomicAdd(&s_n2, 1u);
            if (pos < CAND2) cand2[pos] = key;
        }
    }
    __syncthreads();
    const int n = min((int)min(s_n2, (unsigned)CAND2), KTOP);

    // ---- register bitonic sort of 256 keys (asc); shfl intra-warp ----
    unsigned long long key = cand2[tid];
    for (int kk = 2; kk <= 256; kk <<= 1) {
        bool up = ((tid & kk) == 0);
        for (int jj = kk >> 1; jj > 0; jj >>= 1) {
            unsigned long long partner;
            if (jj >= 32) {
                __syncthreads();
                cand2[tid] = key;
                __syncthreads();
                partner = cand2[tid ^ jj];
            } else {
                partner = __shfl_xor_sync(0xFFFFFFFFu, key, jj);
            }
            bool takeMin = (((tid & jj) == 0) == up);
            bool sw = takeMin ? (partner < key) : (partner > key);
            if (sw) key = partner;
        }
    }

    // ---- extract top-n (descending) and zero the mask (overlays buf) ----
    unsigned long long (*mask)[4] = (unsigned long long (*)[4])buf;
    {
        int k = 255 - tid;                    // descending rank of this thread's key
        if (k < n) {
            unsigned bits = (unsigned)(key >> 32);
            int p = (int)(~(unsigned)key);
            float4 bx = g_boxes[b * PRI + p];
            sBox[k]   = bx;
            sScore[k] = __uint_as_float(bits);
            sArea[k]  = (bx.z - bx.x) * (bx.w - bx.y);
        }
        for (int t = tid; t < KTOP * 4; t += 256)
            ((unsigned long long*)mask)[t] = 0ULL;
    }
    __syncthreads();

    // ---- suppression bitmask: rows interleaved over warps, no barriers ----
    for (int i = wid; i < n; i += 8) {
        float4 bi = sBox[i];
        float  ai = sArea[i];
        for (int j = i + 1 + lane; j < n; j += 32) {
            float4 bj = sBox[j];
            float w = fminf(bi.z, bj.z) - fmaxf(bi.x, bj.x);
            float h = fminf(bi.w, bj.w) - fmaxf(bi.y, bj.y);
            w = fmaxf(w, 0.0f); h = fmaxf(h, 0.0f);
            float inter = w * h;
            if (inter > NMS_TH * (ai + sArea[j] - inter))
                atomicOr(&mask[i][j >> 6], 1ULL << (j & 63));
        }
    }
    __syncthreads();

    // ---- serial greedy scan over 4x64-bit keep words ----
    if (tid == 0) {
        unsigned long long kw[4];
        #pragma unroll
        for (int q = 0; q < 4; q++) {
            int rem = n - q * 64;
            kw[q] = (rem >= 64) ? ~0ULL : (rem > 0 ? ((1ULL << rem) - 1ULL) : 0ULL);
        }
        for (int i = 0; i < n; i++) {
            if ((kw[i >> 6] >> (i & 63)) & 1ULL) {
                kw[0] &= ~mask[i][0]; kw[1] &= ~mask[i][1];
                kw[2] &= ~mask[i][2]; kw[3] &= ~mask[i][3];
            }
        }
        sKeepW[0] = kw[0]; sKeepW[1] = kw[1]; sKeepW[2] = kw[2]; sKeepW[3] = kw[3];
    }
    __syncthreads();

    // ---- write slab: zero 200x5, then scatter kept rows to front ----
    float* outBase = out + (size_t)(b * NCLS_TOT + cc + 1) * KTOP * 5;
    for (int t = tid; t < KTOP * 5; t += 256) outBase[t] = 0.0f;
    __syncthreads();

    for (int k = tid; k < n; k += 256) {
        unsigned long long w = sKeepW[k >> 6];
        if ((w >> (k & 63)) & 1ULL) {
            int d = 0;
            for (int q = 0; q < (k >> 6); q++) d += __popcll(sKeepW[q]);
            unsigned long long below = (k & 63) ? (w & ((1ULL << (k & 63)) - 1ULL)) : 0ULL;
            d += __popcll(below);
            float* r = outBase + d * 5;
            float4 bx = sBox[k];
            r[0] = sScore[k];
            r[1] = bx.x; r[2] = bx.y; r[3] = bx.z; r[4] = bx.w;
        }
    }
}

// ---------------------------------------------------------------------------
extern "C" void kernel_launch(void* const* d_in, const int* in_sizes, int n_in,
                              void* d_out, int out_size) {
    const float4* loc   = (const float4*)d_in[0];   // [B, P, 4]
    const float*  conf  = (const float*)d_in[1];    // [B*P, C]
    const float4* prior = (const float4*)d_in[2];   // [P, 4]
    float* out = (float*)d_out;                     // [B, C, K, 5]

    decode_kernel<<<(BATCH * PRI + 255) / 256, 256>>>(loc, prior);

    dim3 tg((PRI + 63) / 64, BATCH);
    transpose_kernel<<<tg, 256>>>(conf);

    zero_bg_kernel<<<(BATCH * KTOP * 5 + 255) / 256, 256>>>(out);

    nms_kernel<<<BATCH * NCLS, 256>>>(out);
}

// round 3
// speedup vs baseline: 1.4560x; 1.1402x over previous
#include <cuda_runtime.h>
#include <math.h>

#define BATCH 32
#define PRI   8732
#define PRI4  (PRI / 4)     // 2183
#define NCLS_TOT 81
#define NCLS  80            // classes 1..80 (class 0 = background, all zeros)
#define KTOP  200
#define CONF_TH 0.01f
#define NMS_TH  0.45f
#define CAND_MAX 1024       // coarse candidate cap
#define CAND2   256         // refined candidate cap (sorted set)
#define NBINS 4096

// Scratch (allocation-free rule: __device__ globals)
__device__ float  g_scoresT[(size_t)BATCH * NCLS * PRI];   // [b][c-1][p], thresholded
__device__ float4 g_boxes[BATCH * PRI];                    // decoded corner-form boxes

// ---------------------------------------------------------------------------
__global__ void decode_kernel(const float4* __restrict__ loc,
                              const float4* __restrict__ priors) {
    int i = blockIdx.x * blockDim.x + threadIdx.x;
    if (i >= BATCH * PRI) return;
    int p = i % PRI;
    float4 l  = loc[i];
    float4 pr = priors[p];
    float cx = pr.x + (l.x * 0.1f) * pr.z;
    float cy = pr.y + (l.y * 0.1f) * pr.w;
    float w  = pr.z * expf(l.z * 0.2f);
    float h  = pr.w * expf(l.w * 0.2f);
    float x1 = cx - w * 0.5f;
    float y1 = cy - h * 0.5f;
    g_boxes[i] = make_float4(x1, y1, x1 + w, y1 + h);
}

// ---------------------------------------------------------------------------
__global__ void transpose_kernel(const float* __restrict__ conf) {
    __shared__ float tile[64 * NCLS_TOT];
    int b  = blockIdx.y;
    int p0 = blockIdx.x * 64;
    int nr = min(64, PRI - p0);
    const float* src = conf + (size_t)(b * PRI + p0) * NCLS_TOT;
    for (int t = threadIdx.x; t < nr * NCLS_TOT; t += blockDim.x) {
        float v = src[t];
        tile[t] = (v > CONF_TH) ? v : 0.0f;
    }
    __syncthreads();
    for (int t = threadIdx.x; t < nr * NCLS; t += blockDim.x) {
        int cc = t / nr;
        int r  = t % nr;
        g_scoresT[(size_t)(b * NCLS + cc) * PRI + p0 + r] = tile[r * NCLS_TOT + cc + 1];
    }
}

// ---------------------------------------------------------------------------
__global__ void zero_bg_kernel(float* __restrict__ out) {
    int i = blockIdx.x * blockDim.x + threadIdx.x;
    if (i >= BATCH * KTOP * 5) return;
    int b = i / (KTOP * 5);
    int r = i % (KTOP * 5);
    out[(size_t)b * NCLS_TOT * KTOP * 5 + r] = 0.0f;
}

// ---------------------------------------------------------------------------
// Per-(b,c): coarse hist (f4 pass) -> parallel-scan cut -> gather (f4 pass) ->
// fine hist (SMEM) -> compact<=256 -> register bitonic sort -> suppression
// bitmask -> serial greedy scan -> popcount compaction -> write 200x5 slab.
//
// SMEM overlays (25.3 KB total => 8 blocks/SM):
//   histM (16 KB): coarse hist, then fine hist, then {cand2 | sBox | sScore}
//   buf   (8 KB):  coarse candidates, then mask[KTOP][4]
// ---------------------------------------------------------------------------
__global__ void __launch_bounds__(256, 8) nms_kernel(float* __restrict__ out) {
    __shared__ unsigned histM[NBINS];                // 16 KB (overlaid, see above)
    __shared__ unsigned long long buf[CAND_MAX];     // 8 KB  (overlaid)
    __shared__ unsigned chunkS[257];                 // suffix sums; [256] stays 0
    __shared__ unsigned long long sKeepW[4];
    __shared__ unsigned s_binT, s_above, s_fcut, s_ncand, s_n2;
    __shared__ int s_found;

    // overlay views into histM (byte offsets: 0, 2048, 5248)
    unsigned long long* cand2 = (unsigned long long*)histM;      // 256 u64 = 2 KB
    float4* sBox  = (float4*)(histM + 512);                      // 200 f4  = 3.2 KB
    float*  sScore = (float*)(histM + 512 + 800);                // 200 f   = 0.8 KB
    unsigned long long (*mask)[4] = (unsigned long long (*)[4])buf;  // 200x4 u64 = 6.4 KB

    const int task = blockIdx.x;
    const int b    = task / NCLS;
    const int cc   = task % NCLS;
    const int tid  = threadIdx.x;
    const int wid  = tid >> 5;
    const int lane = tid & 31;
    const float4* sc4 = (const float4*)(g_scoresT + (size_t)task * PRI);

    for (int t = tid; t < NBINS; t += 256) histM[t] = 0;
    if (tid == 0) { s_ncand = 0; s_n2 = 0; s_found = 0; s_binT = 0; s_above = 0; chunkS[256] = 0; }
    __syncthreads();

    // ---- coarse histogram on top-12 bits of positive float pattern ----
    for (int i = tid; i < PRI4; i += 256) {
        float4 v = sc4[i];
        if (v.x > 0.0f) atomicAdd(&histM[__float_as_uint(v.x) >> 20], 1u);
        if (v.y > 0.0f) atomicAdd(&histM[__float_as_uint(v.y) >> 20], 1u);
        if (v.z > 0.0f) atomicAdd(&histM[__float_as_uint(v.z) >> 20], 1u);
        if (v.w > 0.0f) atomicAdd(&histM[__float_as_uint(v.w) >> 20], 1u);
    }
    __syncthreads();

    // ---- parallel cut-find: chunk sums -> suffix scan -> winner refines ----
    {
        unsigned part = 0;
        #pragma unroll
        for (int r = 0; r < NBINS / 256; r++) part += histM[tid * (NBINS / 256) + r];
        chunkS[tid] = part;
        __syncthreads();
        for (int d = 1; d < 256; d <<= 1) {
            unsigned v = chunkS[tid] + ((tid + d < 256) ? chunkS[tid + d] : 0u);
            __syncthreads();
            chunkS[tid] = v;
            __syncthreads();
        }
        if (chunkS[tid] >= KTOP && chunkS[tid + 1] < KTOP) {   // unique winner
            unsigned cum = chunkS[tid + 1];
            for (int bb = tid * 16 + 15; bb >= tid * 16; bb--) {
                cum += histM[bb];
                if (cum >= KTOP) {
                    s_binT  = (unsigned)bb;
                    s_above = cum - histM[bb];
                    s_found = 1;
                    break;
                }
            }
        }
        __syncthreads();
    }
    const unsigned binT = s_binT;
    const int found = s_found;

    // ---- gather coarse candidates (bins >= binT) ----
    for (int i = tid; i < PRI4; i += 256) {
        float4 v = sc4[i];
        int p = i * 4;
        #pragma unroll
        for (int c = 0; c < 4; c++) {
            float vv = (c == 0) ? v.x : (c == 1) ? v.y : (c == 2) ? v.z : v.w;
            if (vv > 0.0f) {
                unsigned bits = __float_as_uint(vv);
                if ((bits >> 20) >= binT) {
                    unsigned pos = atomicAdd(&s_ncand, 1u);
                    if (pos < CAND_MAX)
                        buf[pos] = ((unsigned long long)bits << 32) | (unsigned)(~(unsigned)(p + c));
                }
            }
        }
    }
    __syncthreads();
    const int gcount = (int)min(s_ncand, (unsigned)CAND_MAX);

    // ---- fine refinement (next 12 bits) within cut bin, SMEM only ----
    if (found) {
        const unsigned above = s_above;
        for (int t = tid; t < NBINS; t += 256) histM[t] = 0;
        __syncthreads();
        for (int t = tid; t < gcount; t += 256) {
            unsigned bits = (unsigned)(buf[t] >> 32);
            if ((bits >> 20) == binT) atomicAdd(&histM[(bits >> 8) & 0xFFFu], 1u);
        }
        __syncthreads();
        unsigned fp = 0;
        #pragma unroll
        for (int r = 0; r < NBINS / 256; r++) fp += histM[tid * (NBINS / 256) + r];
        chunkS[tid] = fp;
        __syncthreads();
        for (int d = 1; d < 256; d <<= 1) {
            unsigned v = chunkS[tid] + ((tid + d < 256) ? chunkS[tid + d] : 0u);
            __syncthreads();
            chunkS[tid] = v;
            __syncthreads();
        }
        const unsigned need = KTOP - above;
        if (chunkS[tid] >= need && chunkS[tid + 1] < need) {
            unsigned cum = chunkS[tid + 1];
            for (int bb = tid * 16 + 15; bb >= tid * 16; bb--) {
                cum += histM[bb];
                if (cum >= need) { s_fcut = (unsigned)bb; break; }
            }
        }
        __syncthreads();
    }
    const unsigned fcut = found ? s_fcut : 0u;
    __syncthreads();          // histM writes done before cand2 overlay reuse

    // ---- compact refined candidates into cand2 (<=256, overlays histM) ----
    for (int t = tid; t < CAND2; t += 256) cand2[t] = 0ULL;
    __syncthreads();
    for (int t = tid; t < gcount; t += 256) {
        unsigned long long key = buf[t];
        unsigned bits = (unsigned)(key >> 32);
        unsigned cb = bits >> 20;
        if (cb > binT || (cb == binT && ((bits >> 8) & 0xFFFu) >= fcut)) {
            unsigned pos = atomicAdd(&s_n2, 1u);
            if (pos < CAND2) cand2[pos] = key;
        }
    }
    __syncthreads();
    const int n = min((int)min(s_n2, (unsigned)CAND2), KTOP);

    // ---- register bitonic sort of 256 keys (asc); shfl intra-warp ----
    unsigned long long key = cand2[tid];
    for (int kk = 2; kk <= 256; kk <<= 1) {
        bool up = ((tid & kk) == 0);
        for (int jj = kk >> 1; jj > 0; jj >>= 1) {
            unsigned long long partner;
            if (jj >= 32) {
                __syncthreads();
                cand2[tid] = key;
                __syncthreads();
                partner = cand2[tid ^ jj];
            } else {
                partner = __shfl_xor_sync(0xFFFFFFFFu, key, jj);
            }
            bool takeMin = (((tid & jj) == 0) == up);
            bool sw = takeMin ? (partner < key) : (partner > key);
            if (sw) key = partner;
        }
    }
    __syncthreads();          // cand2 reads done; sBox/sScore overlay safe

    // ---- extract top-n (descending) ; zero the mask (overlays buf) ----
    {
        int k = 255 - tid;                    // descending rank of this thread's key
        if (k < n) {
            unsigned bits = (unsigned)(key >> 32);
            int p = (int)(~(unsigned)key);
            float4 bx = g_boxes[b * PRI + p];
            sBox[k]   = bx;
            sScore[k] = __uint_as_float(bits);
        }
        for (int t = tid; t < KTOP * 4; t += 256)
            ((unsigned long long*)mask)[t] = 0ULL;
    }
    __syncthreads();

    // ---- suppression bitmask: rows interleaved over warps, no barriers ----
    for (int i = wid; i < n; i += 8) {
        float4 bi = sBox[i];
        float  ai = (bi.z - bi.x) * (bi.w - bi.y);
        for (int j = i + 1 + lane; j < n; j += 32) {
            float4 bj = sBox[j];
            float aj = (bj.z - bj.x) * (bj.w - bj.y);
            float w = fminf(bi.z, bj.z) - fmaxf(bi.x, bj.x);
            float h = fminf(bi.w, bj.w) - fmaxf(bi.y, bj.y);
            w = fmaxf(w, 0.0f); h = fmaxf(h, 0.0f);
            float inter = w * h;
            if (inter > NMS_TH * (ai + aj - inter))
                atomicOr(&mask[i][j >> 6], 1ULL << (j & 63));
        }
    }
    __syncthreads();

    // ---- serial greedy scan over 4x64-bit keep words ----
    if (tid == 0) {
        unsigned long long kw[4];
        #pragma unroll
        for (int q = 0; q < 4; q++) {
            int rem = n - q * 64;
            kw[q] = (rem >= 64) ? ~0ULL : (rem > 0 ? ((1ULL << rem) - 1ULL) : 0ULL);
        }
        for (int i = 0; i < n; i++) {
            if ((kw[i >> 6] >> (i & 63)) & 1ULL) {
                kw[0] &= ~mask[i][0]; kw[1] &= ~mask[i][1];
                kw[2] &= ~mask[i][2]; kw[3] &= ~mask[i][3];
            }
        }
        sKeepW[0] = kw[0]; sKeepW[1] = kw[1]; sKeepW[2] = kw[2]; sKeepW[3] = kw[3];
    }
    __syncthreads();

    // ---- write slab: vector-zero 200x5, then scatter kept rows to front ----
    float* outBase = out + (size_t)(b * NCLS_TOT + cc + 1) * KTOP * 5;
    float4* outBase4 = (float4*)outBase;               // 1000 floats = 250 f4, 16B-aligned
    for (int t = tid; t < KTOP * 5 / 4; t += 256) outBase4[t] = make_float4(0.f, 0.f, 0.f, 0.f);
    __syncthreads();

    for (int k = tid; k < n; k += 256) {
        unsigned long long w = sKeepW[k >> 6];
        if ((w >> (k & 63)) & 1ULL) {
            int d = 0;
            for (int q = 0; q < (k >> 6); q++) d += __popcll(sKeepW[q]);
            unsigned long long below = (k & 63) ? (w & ((1ULL << (k & 63)) - 1ULL)) : 0ULL;
            d += __popcll(below);
            float* r = outBase + d * 5;
            float4 bx = sBox[k];
            r[0] = sScore[k];
            r[1] = bx.x; r[2] = bx.y; r[3] = bx.z; r[4] = bx.w;
        }
    }
}

// ---------------------------------------------------------------------------
extern "C" void kernel_launch(void* const* d_in, const int* in_sizes, int n_in,
                              void* d_out, int out_size) {
    const float4* loc   = (const float4*)d_in[0];   // [B, P, 4]
    const float*  conf  = (const float*)d_in[1];    // [B*P, C]
    const float4* prior = (const float4*)d_in[2];   // [P, 4]
    float* out = (float*)d_out;                     // [B, C, K, 5]

    decode_kernel<<<(BATCH * PRI + 255) / 256, 256>>>(loc, prior);

    dim3 tg((PRI + 63) / 64, BATCH);
    transpose_kernel<<<tg, 256>>>(conf);

    zero_bg_kernel<<<(BATCH * KTOP * 5 + 255) / 256, 256>>>(out);

    nms_kernel<<<BATCH * NCLS, 256>>>(out);
}